// round 16
// baseline (speedup 1.0000x reference)
#include <cuda_runtime.h>
#include <cuda_bf16.h>
#include <cstdint>

// Problem constants (fixed by dataset): b=4, n=4096 -> M=16384 tokens, d=256, h=8
#define D    256
#define H    8
#define HD   2048
#define MAXM 16384

// Scratch (device globals: allocation-free rule)
__device__ float g_qkv[(size_t)MAXM * 3 * HD];            // fp32 q|k|v per token
__device__ __nv_bfloat16 g_xhi[(size_t)MAXM * D];         // hi/lo split of X
__device__ __nv_bfloat16 g_xlo[(size_t)MAXM * D];
__device__ __nv_bfloat16 g_whi[(size_t)3 * D * HD];       // Wq|Wk|Wv hi
__device__ __nv_bfloat16 g_wlo[(size_t)3 * D * HD];       // Wq|Wk|Wv lo
__device__ __nv_bfloat16 g_wohi[(size_t)HD * D];
__device__ __nv_bfloat16 g_wolo[(size_t)HD * D];
__device__ __nv_bfloat16 g_o1hi[(size_t)MAXM * HD];       // attn out hi/lo
__device__ __nv_bfloat16 g_o1lo[(size_t)MAXM * HD];

__device__ __forceinline__ void pack_hilo(float x, float y,
                                          uint32_t& hi, uint32_t& lo) {
    __nv_bfloat16 hx = __float2bfloat16_rn(x);
    __nv_bfloat16 hy = __float2bfloat16_rn(y);
    __nv_bfloat162 h2; h2.x = hx; h2.y = hy;
    hi = *(uint32_t*)&h2;
    __nv_bfloat162 l2 = __float22bfloat162_rn(
        make_float2(x - __bfloat162float(hx), y - __bfloat162float(hy)));
    lo = *(uint32_t*)&l2;
}

// ---------------------------------------------------------------------------
// Elementwise fp32 -> (bf16 hi, bf16 lo) conversion, float4-vectorized.
// ---------------------------------------------------------------------------
__global__ void cvt_hilo(const float* __restrict__ src,
                         __nv_bfloat16* __restrict__ hi,
                         __nv_bfloat16* __restrict__ lo, int n4)
{
    int i = blockIdx.x * blockDim.x + threadIdx.x;
    if (i < n4) {
        float4 v = ((const float4*)src)[i];
        uint32_t h0, l0, h1, l1;
        pack_hilo(v.x, v.y, h0, l0);
        pack_hilo(v.z, v.w, h1, l1);
        ((uint2*)hi)[i] = make_uint2(h0, h1);
        ((uint2*)lo)[i] = make_uint2(l0, l1);
    }
}

// ---------------------------------------------------------------------------
// bf16-split GEMM v4:  C = A@B + bias  ==  Ahi·Bhi + Alo·Bhi + Ahi·Blo
// Inputs are PRE-SPLIT bf16 (hi/lo). Tiles staged with cp.async.cg (16B):
// no STS, no in-loop conversion. Double-buffered, 1 barrier/k-block.
// Tile: 128x128 CTA, k-block 16, 8 warps (4M x 2N), warp = 32x64.
// ---------------------------------------------------------------------------
#define GBM 128
#define GBN 128
#define BKO 16     // k per stage
#define LDSA2 24   // halves per A row (stride 12 words: ldsm conflict-free)
#define LDSB2 136  // halves per B row [k][n] (stride 68 words: conflict-free)

__device__ __forceinline__ void cp16(uint32_t dst, const void* src) {
    asm volatile("cp.async.cg.shared.global [%0], [%1], 16;\n"
                 :: "r"(dst), "l"(src) : "memory");
}
__device__ __forceinline__ void cp_commit() {
    asm volatile("cp.async.commit_group;\n" ::: "memory");
}
__device__ __forceinline__ void cp_wait0() {
    asm volatile("cp.async.wait_group 0;\n" ::: "memory");
}

__device__ __forceinline__ void mma16816(float c[4], const uint32_t a[4],
                                         uint32_t b0, uint32_t b1) {
    asm volatile(
        "mma.sync.aligned.m16n8k16.row.col.f32.bf16.bf16.f32 "
        "{%0,%1,%2,%3}, {%4,%5,%6,%7}, {%8,%9}, {%0,%1,%2,%3};\n"
        : "+f"(c[0]), "+f"(c[1]), "+f"(c[2]), "+f"(c[3])
        : "r"(a[0]), "r"(a[1]), "r"(a[2]), "r"(a[3]), "r"(b0), "r"(b1));
}

__device__ __forceinline__ void ldsm_x4(uint32_t r[4], uint32_t addr) {
    asm volatile("ldmatrix.sync.aligned.m8n8.x4.shared.b16 {%0,%1,%2,%3}, [%4];"
                 : "=r"(r[0]), "=r"(r[1]), "=r"(r[2]), "=r"(r[3]) : "r"(addr));
}
__device__ __forceinline__ void ldsm_x4_t(uint32_t r[4], uint32_t addr) {
    asm volatile("ldmatrix.sync.aligned.m8n8.x4.trans.shared.b16 {%0,%1,%2,%3}, [%4];"
                 : "=r"(r[0]), "=r"(r[1]), "=r"(r[2]), "=r"(r[3]) : "r"(addr));
}

__global__ void __launch_bounds__(256)
gemm_bf16v4(const __nv_bfloat16* __restrict__ Ahi, const __nv_bfloat16* __restrict__ Alo,
            const __nv_bfloat16* __restrict__ Bh0, const __nv_bfloat16* __restrict__ Bl0,
            const float* __restrict__ bias0,
            const __nv_bfloat16* __restrict__ Bh1, const __nv_bfloat16* __restrict__ Bl1,
            const float* __restrict__ bias1,
            const __nv_bfloat16* __restrict__ Bh2, const __nv_bfloat16* __restrict__ Bl2,
            const float* __restrict__ bias2,
            float* __restrict__ C, int c_zstride,
            int K, int lda, int ldb, int ldc)
{
    __shared__ __align__(16) __nv_bfloat16 Ah[2][GBM * LDSA2];
    __shared__ __align__(16) __nv_bfloat16 Al[2][GBM * LDSA2];
    __shared__ __align__(16) __nv_bfloat16 Bh[2][BKO * LDSB2];
    __shared__ __align__(16) __nv_bfloat16 Bl[2][BKO * LDSB2];

    const int t    = threadIdx.x;
    const int lane = t & 31;
    const int w    = t >> 5;
    const int wm   = w & 3;          // warp M index: offset wm*32
    const int wn   = w >> 2;         // warp N index: offset wn*64
    const int g    = lane >> 2;
    const int tg   = lane & 3;
    const int l7   = lane & 7;
    const int sub  = lane >> 3;
    const int mrow = (sub & 1) * 8 + l7;
    const int mcol = (sub >> 1) * 8;

    const int z = blockIdx.z;
    const __nv_bfloat16* Bhz = (z == 0) ? Bh0 : (z == 1) ? Bh1 : Bh2;
    const __nv_bfloat16* Blz = (z == 0) ? Bl0 : (z == 1) ? Bl1 : Bl2;
    const float* bias        = (z == 0) ? bias0 : (z == 1) ? bias1 : bias2;
    float* Cz = C + (size_t)z * c_zstride;

    const __nv_bfloat16* Agh = Ahi + (size_t)blockIdx.y * GBM * lda;
    const __nv_bfloat16* Agl = Alo + (size_t)blockIdx.y * GBM * lda;
    const __nv_bfloat16* Bgh = Bhz + blockIdx.x * GBN;
    const __nv_bfloat16* Bgl = Blz + blockIdx.x * GBN;

    // cp.async coords: A row=t>>1, seg=t&1 (16B=8 halves); B kr=t>>4, seg=t&15
    const int arow = t >> 1, aseg = t & 1;
    const int bkr  = t >> 4, bseg = t & 15;
    const uint32_t a_dst_off = (uint32_t)(arow * LDSA2 + aseg * 8) * 2;
    const uint32_t b_dst_off = (uint32_t)(bkr * LDSB2 + bseg * 8) * 2;
    const uint32_t sAh[2] = { (uint32_t)__cvta_generic_to_shared(&Ah[0][0]) + a_dst_off,
                              (uint32_t)__cvta_generic_to_shared(&Ah[1][0]) + a_dst_off };
    const uint32_t sAl[2] = { (uint32_t)__cvta_generic_to_shared(&Al[0][0]) + a_dst_off,
                              (uint32_t)__cvta_generic_to_shared(&Al[1][0]) + a_dst_off };
    const uint32_t sBh[2] = { (uint32_t)__cvta_generic_to_shared(&Bh[0][0]) + b_dst_off,
                              (uint32_t)__cvta_generic_to_shared(&Bh[1][0]) + b_dst_off };
    const uint32_t sBl[2] = { (uint32_t)__cvta_generic_to_shared(&Bl[0][0]) + b_dst_off,
                              (uint32_t)__cvta_generic_to_shared(&Bl[1][0]) + b_dst_off };

    float acc[2][8][4];
#pragma unroll
    for (int mt = 0; mt < 2; mt++)
#pragma unroll
        for (int nt = 0; nt < 8; nt++)
#pragma unroll
            for (int i = 0; i < 4; i++) acc[mt][nt][i] = 0.0f;

    const int nblocks = K / BKO;

    // ---- prologue: async-stage k-block 0 into buf 0 ----
    cp16(sAh[0], Agh + (size_t)arow * lda + aseg * 8);
    cp16(sAl[0], Agl + (size_t)arow * lda + aseg * 8);
    cp16(sBh[0], Bgh + (size_t)bkr * ldb + bseg * 8);
    cp16(sBl[0], Bgl + (size_t)bkr * ldb + bseg * 8);
    cp_commit();
    cp_wait0();
    __syncthreads();

    for (int kb = 0; kb < nblocks; kb++) {
        const int cur = kb & 1;
        const int nxt = cur ^ 1;
        const int kb1 = kb + 1;

        // ---- issue async stage of k-block kb+1 into buf nxt ----
        if (kb1 < nblocks) {
            const int bk1 = kb1 * BKO;
            cp16(sAh[nxt], Agh + (size_t)arow * lda + bk1 + aseg * 8);
            cp16(sAl[nxt], Agl + (size_t)arow * lda + bk1 + aseg * 8);
            cp16(sBh[nxt], Bgh + (size_t)(bk1 + bkr) * ldb + bseg * 8);
            cp16(sBl[nxt], Bgl + (size_t)(bk1 + bkr) * ldb + bseg * 8);
            cp_commit();
        }

        // ---- compute: 3 MMA groups on staged tiles (k = 16) ----
        {
            uint32_t ah[2][4], al[2][4];
#pragma unroll
            for (int mt = 0; mt < 2; mt++) {
                const int aoff = (wm * 32 + mt * 16 + mrow) * LDSA2 + mcol;
                ldsm_x4(ah[mt], (uint32_t)__cvta_generic_to_shared(&Ah[cur][aoff]));
                ldsm_x4(al[mt], (uint32_t)__cvta_generic_to_shared(&Al[cur][aoff]));
            }
#pragma unroll
            for (int ntp = 0; ntp < 4; ntp++) {
                uint32_t bh[4], bl[4];
                const int boff = mrow * LDSB2 + wn * 64 + ntp * 16 + mcol;
                ldsm_x4_t(bh, (uint32_t)__cvta_generic_to_shared(&Bh[cur][boff]));
                ldsm_x4_t(bl, (uint32_t)__cvta_generic_to_shared(&Bl[cur][boff]));
#pragma unroll
                for (int mt = 0; mt < 2; mt++) {
                    mma16816(acc[mt][ntp * 2 + 0], ah[mt], bh[0], bh[1]);
                    mma16816(acc[mt][ntp * 2 + 0], al[mt], bh[0], bh[1]);
                    mma16816(acc[mt][ntp * 2 + 0], ah[mt], bl[0], bl[1]);
                    mma16816(acc[mt][ntp * 2 + 1], ah[mt], bh[2], bh[3]);
                    mma16816(acc[mt][ntp * 2 + 1], al[mt], bh[2], bh[3]);
                    mma16816(acc[mt][ntp * 2 + 1], ah[mt], bl[2], bl[3]);
                }
            }
        }

        if (kb1 < nblocks) {
            cp_wait0();          // k-block kb+1 landed
            __syncthreads();     // visible to all; fences buf reuse
        }
    }

    // ---- epilogue: + bias, float2 stores ----
    const int row_base = blockIdx.y * GBM + wm * 32 + g;
    const int col_base = blockIdx.x * GBN + wn * 64 + tg * 2;
#pragma unroll
    for (int nt = 0; nt < 8; nt++) {
        const int col = col_base + nt * 8;
        const float b0 = bias[col], b1 = bias[col + 1];
#pragma unroll
        for (int mt = 0; mt < 2; mt++) {
            const int r = row_base + mt * 16;
            float2 v0 = make_float2(acc[mt][nt][0] + b0, acc[mt][nt][1] + b1);
            float2 v1 = make_float2(acc[mt][nt][2] + b0, acc[mt][nt][3] + b1);
            *(float2*)(Cz + (size_t)r * ldc + col)       = v0;
            *(float2*)(Cz + (size_t)(r + 8) * ldc + col) = v1;
        }
    }
}

// ---------------------------------------------------------------------------
// Per-token head-vs-head attention (fp32 math). Writes o1 as bf16 hi+lo
// (same split the GEMM would have computed — numerics unchanged).
// ---------------------------------------------------------------------------
__global__ void __launch_bounds__(256)
attn_kernel(const float* __restrict__ qkv,
            __nv_bfloat16* __restrict__ o1hi, __nv_bfloat16* __restrict__ o1lo)
{
    __shared__ float s[3 * HD];
    const size_t tok = blockIdx.x;

    const float4* src = (const float4*)(qkv + tok * (size_t)(3 * HD));
    float4* dst = (float4*)s;
#pragma unroll
    for (int i = threadIdx.x; i < (3 * HD) / 4; i += 256) dst[i] = src[i];
    __syncthreads();

    const float* sq = s;
    const float* sk = s + HD;
    const float* sv = s + 2 * HD;

    const int w    = threadIdx.x >> 5;
    const int lane = threadIdx.x & 31;
    const float scale = 0.0625f;   // 1/sqrt(256)

    float a[H];
#pragma unroll
    for (int gg = 0; gg < H; gg++) {
        float sum = 0.0f;
#pragma unroll
        for (int m = 0; m < 8; m++) {
            const int dd = lane + 32 * m;
            sum += sq[w * D + dd] * sk[gg * D + dd];
        }
#pragma unroll
        for (int off = 16; off; off >>= 1)
            sum += __shfl_xor_sync(0xffffffffu, sum, off);
        a[gg] = sum * scale;
    }

    float mx = a[0];
#pragma unroll
    for (int gg = 1; gg < H; gg++) mx = fmaxf(mx, a[gg]);
    float ssum = 0.0f;
#pragma unroll
    for (int gg = 0; gg < H; gg++) { a[gg] = expf(a[gg] - mx); ssum += a[gg]; }
    const float inv = 1.0f / ssum;
#pragma unroll
    for (int gg = 0; gg < H; gg++) a[gg] *= inv;

    const size_t obase = tok * (size_t)HD + w * D;
#pragma unroll
    for (int m = 0; m < 8; m++) {
        const int dd = lane + 32 * m;
        float o = 0.0f;
#pragma unroll
        for (int gg = 0; gg < H; gg++) o += a[gg] * sv[gg * D + dd];
        __nv_bfloat16 h = __float2bfloat16_rn(o);
        __nv_bfloat16 l = __float2bfloat16_rn(o - __bfloat162float(h));
        o1hi[obase + dd] = h;
        o1lo[obase + dd] = l;
    }
}

// ---------------------------------------------------------------------------
extern "C" void kernel_launch(void* const* d_in, const int* in_sizes, int n_in,
                              void* d_out, int out_size)
{
    const float* x  = (const float*)d_in[0];
    const float* Wq = (const float*)d_in[1];
    const float* bq = (const float*)d_in[2];
    const float* Wk = (const float*)d_in[3];
    const float* bk = (const float*)d_in[4];
    const float* Wv = (const float*)d_in[5];
    const float* bv = (const float*)d_in[6];
    const float* Wo = (const float*)d_in[7];
    const float* bo = (const float*)d_in[8];
    float* out = (float*)d_out;

    const int M = in_sizes[0] / D;   // 16384 tokens

    float *qkv;
    __nv_bfloat16 *xhi, *xlo, *whi, *wlo, *wohi, *wolo, *o1hi, *o1lo;
    cudaGetSymbolAddress((void**)&qkv,  g_qkv);
    cudaGetSymbolAddress((void**)&xhi,  g_xhi);
    cudaGetSymbolAddress((void**)&xlo,  g_xlo);
    cudaGetSymbolAddress((void**)&whi,  g_whi);
    cudaGetSymbolAddress((void**)&wlo,  g_wlo);
    cudaGetSymbolAddress((void**)&wohi, g_wohi);
    cudaGetSymbolAddress((void**)&wolo, g_wolo);
    cudaGetSymbolAddress((void**)&o1hi, g_o1hi);
    cudaGetSymbolAddress((void**)&o1lo, g_o1lo);

    dim3 blk(256);

    // ---- pre-split fp32 -> bf16 hi/lo ----
    const int xn4 = (M * D) / 4;
    cvt_hilo<<<(xn4 + 255) / 256, blk>>>(x, xhi, xlo, xn4);
    const int wn4 = (D * HD) / 4;
    cvt_hilo<<<(wn4 + 255) / 256, blk>>>(Wq, whi + 0 * (size_t)D * HD, wlo + 0 * (size_t)D * HD, wn4);
    cvt_hilo<<<(wn4 + 255) / 256, blk>>>(Wk, whi + 1 * (size_t)D * HD, wlo + 1 * (size_t)D * HD, wn4);
    cvt_hilo<<<(wn4 + 255) / 256, blk>>>(Wv, whi + 2 * (size_t)D * HD, wlo + 2 * (size_t)D * HD, wn4);
    cvt_hilo<<<(wn4 + 255) / 256, blk>>>(Wo, wohi, wolo, wn4);

    // ---- fused QKV projections ----
    dim3 gA(HD / GBN, M / GBM, 3);
    gemm_bf16v4<<<gA, blk>>>(xhi, xlo,
                             whi + 0 * (size_t)D * HD, wlo + 0 * (size_t)D * HD, bq,
                             whi + 1 * (size_t)D * HD, wlo + 1 * (size_t)D * HD, bk,
                             whi + 2 * (size_t)D * HD, wlo + 2 * (size_t)D * HD, bv,
                             qkv, HD, D, D, HD, 3 * HD);

    // ---- per-token attention (writes o1 hi/lo) ----
    attn_kernel<<<M, blk>>>(qkv, o1hi, o1lo);

    // ---- output projection ----
    dim3 gC(D / GBN, M / GBM, 1);
    gemm_bf16v4<<<gC, blk>>>(o1hi, o1lo,
                             wohi, wolo, bo, wohi, wolo, bo, wohi, wolo, bo,
                             out, 0, HD, HD, D, D);
}